// round 1
// baseline (speedup 1.0000x reference)
#include <cuda_runtime.h>
#include <cstdint>

#define NTT 144
#define NTERMS 22                 // series coefficients d0..d21
#define ROWS_PER_BLK 8
#define THREADS_PER_ROW 36        // 36 * 4 elems = 144
#define BLK (ROWS_PER_BLK * THREADS_PER_ROW)  // 288

#define F_TAU 1.8f
#define F_INV_T1B (1.0f/1.65f)
#define F_LOG2E 1.4426950408889634f
#define F_DEG2RAD 0.017453292519943295f

__device__ __forceinline__ unsigned long long pack2(float lo, float hi) {
    unsigned long long r;
    asm("mov.b64 %0, {%1, %2};" : "=l"(r) : "f"(lo), "f"(hi));
    return r;
}
__device__ __forceinline__ void unpack2(unsigned long long v, float& lo, float& hi) {
    asm("mov.b64 {%0, %1}, %2;" : "=f"(lo), "=f"(hi) : "l"(v));
}
__device__ __forceinline__ unsigned long long ffma2(unsigned long long a,
                                                    unsigned long long b,
                                                    unsigned long long c) {
    unsigned long long d;
    asm("fma.rn.f32x2 %0, %1, %2, %3;" : "=l"(d) : "l"(a), "l"(b), "l"(c));
    return d;
}
__device__ __forceinline__ float fast_lg2(float x) {
    float r;
    asm("lg2.approx.f32 %0, %1;" : "=f"(r) : "f"(x));
    return r;
}
__device__ __forceinline__ float fast_ex2(float x) {
    float r;
    asm("ex2.approx.f32 %0, %1;" : "=f"(r) : "f"(x));
    return r;
}

__global__ __launch_bounds__(BLK, 2)
void dynangio_kernel(const float4* __restrict__ x,
                     const float*  __restrict__ t,
                     const float*  __restrict__ alpha,
                     const float*  __restrict__ R,
                     float*        __restrict__ out,
                     int rows)
{
    __shared__ __align__(16) float tsh[NTT];
    __shared__ __align__(16) float csh[NTT];
    // per-row constants: [0]=a [1]=sprime [2]=q (=sprime*dt) [3]=shift (=sprime*TAU)
    //                    [4]=C (=amp*SF)  [5..26]=d0..d21
    __shared__ float rc[ROWS_PER_BLK][5 + NTERMS + 1];

    const int tid = threadIdx.x;

    // cooperative: time grid + combined weight c_j = R[j] * sin(deg2rad(alpha[j]))
    for (int j = tid; j < NTT; j += BLK) {
        tsh[j] = t[j];
        csh[j] = R[j] * __sinf(alpha[j] * F_DEG2RAD);
    }

    // per-row precompute (one lane per row)
    if (tid < ROWS_PER_BLK) {
        int row = blockIdx.x * ROWS_PER_BLK + tid;
        if (row < rows) {
            float4 xv = x[row];
            float dt  = xv.x;
            float s   = xv.y;
            float p   = xv.z;
            float amp = xv.w;

            float u  = p * s;          // a - 1 in [0,1)
            float a  = 1.0f + u;
            float sp = s + F_INV_T1B;  // sprime

            // SF = 2 * exp(-dt/T1B) * (s/sp)^a  -> base-2
            float ratio = __fdividef(s, sp);
            float ex = fmaf(a, fast_lg2(ratio), -dt * (F_LOG2E * F_INV_T1B));
            float C  = amp * 2.0f * fast_ex2(ex);

            // Gamma(1+u), A&S 6.1.36 (|err| <= 3e-7 on [0,1])
            float g;
            g = fmaf(u,  0.035868343f, -0.193527818f);
            g = fmaf(u, g,  0.482199394f);
            g = fmaf(u, g, -0.756704078f);
            g = fmaf(u, g,  0.918206857f);
            g = fmaf(u, g, -0.897056937f);
            g = fmaf(u, g,  0.988205891f);
            g = fmaf(u, g, -0.577191652f);
            g = fmaf(u, g,  1.0f);
            // Gamma(a+1) = a * Gamma(a) = a * Gamma(1+u)
            float d = __fdividef(1.0f, a * g);   // d0 = 1/Gamma(a+1)

            rc[tid][0] = a;
            rc[tid][1] = sp;
            rc[tid][2] = sp * dt;
            rc[tid][3] = sp * F_TAU;
            rc[tid][4] = C;
            rc[tid][5] = d;
            #pragma unroll
            for (int n = 1; n < NTERMS; n++) {
                d = __fdividef(d, a + (float)n);   // d_n = 1/Gamma(a+n+1)
                rc[tid][5 + n] = d;
            }
        }
    }
    __syncthreads();

    const int rl  = tid / THREADS_PER_ROW;
    const int l   = tid - rl * THREADS_PER_ROW;
    const int jj  = l * 4;
    const int row = blockIdx.x * ROWS_PER_BLK + rl;
    if (row >= rows) return;

    const float a     = rc[rl][0];
    const float sp    = rc[rl][1];
    const float q     = rc[rl][2];
    const float shift = rc[rl][3];
    const float C     = rc[rl][4];

    unsigned long long D[NTERMS];
    #pragma unroll
    for (int k = 0; k < NTERMS; k++) {
        float dk = rc[rl][5 + k];
        D[k] = pack2(dk, dk);
    }

    const float4 t4 = *reinterpret_cast<const float4*>(tsh + jj);
    const float4 c4 = *reinterpret_cast<const float4*>(csh + jj);
    float tv[4] = {t4.x, t4.y, t4.z, t4.w};
    float cv[4] = {c4.x, c4.y, c4.z, c4.w};
    float res[4];

    #pragma unroll
    for (int e = 0; e < 4; e++) {
        float x1 = fmaf(sp, tv[e], -q);          // sprime*(t_j - dt), > 0 always
        float x2 = fmaxf(x1 - shift, 0.0f);      // clamp as in reference

        // packed Horner: H(x) = sum_n d_n x^n evaluated at (x1, x2) simultaneously
        unsigned long long X = pack2(x1, x2);
        unsigned long long H = D[NTERMS - 1];
        #pragma unroll
        for (int k = NTERMS - 2; k >= 0; k--) H = ffma2(H, X, D[k]);
        float h1, h2;
        unpack2(H, h1, h2);

        // P(a,x) = exp2(a*log2(x) - x*log2e) * H(x)
        float v1 = fmaf(a, fast_lg2(x1), -x1 * F_LOG2E);
        float v2 = fmaf(a, fast_lg2(x2), -x2 * F_LOG2E);
        float P1 = fast_ex2(v1) * h1;
        float P2 = (x2 > 0.0f) ? fast_ex2(v2) * h2 : 0.0f;

        res[e] = (C * cv[e]) * (P1 - P2);
    }

    float4 o = make_float4(res[0], res[1], res[2], res[3]);
    *reinterpret_cast<float4*>(out + (size_t)row * NTT + jj) = o;
}

extern "C" void kernel_launch(void* const* d_in, const int* in_sizes, int n_in,
                              void* d_out, int out_size) {
    const float4* x     = (const float4*)d_in[0];
    const float*  t     = (const float*)d_in[1];
    const float*  alpha = (const float*)d_in[2];
    const float*  R     = (const float*)d_in[3];
    float* out = (float*)d_out;

    int rows   = in_sizes[0] / 4;
    int blocks = (rows + ROWS_PER_BLK - 1) / ROWS_PER_BLK;
    dynangio_kernel<<<blocks, BLK>>>(x, t, alpha, R, out, rows);
}